// round 1
// baseline (speedup 1.0000x reference)
#include <cuda_runtime.h>
#include <math.h>

// ---------------- problem constants ----------------
#define B_   8
#define N_   64
#define E_   192
#define DIN  1024
#define DP   256
#define F_   16
#define NN_  4096
#define TAU  0.05f
#define ROWS_TOT 4096   // 512 + 512 + 1536 + 1536

// ---------------- device scratch (static, allocation-free) ----------------
__device__ float g_H[ROWS_TOT * DP];          // projected rows (in-place normalized)
__device__ float g_mu[4 * DP];
__device__ float g_var[4 * DP];
__device__ float g_Kp[B_ * N_ * N_];
__device__ float g_Ke[B_ * E_ * E_];
__device__ int   g_cnt1[B_ * N_], g_cnt2[B_ * N_];
__device__ int   g_idx1[B_ * N_ * E_], g_idx2[B_ * N_ * E_];
__device__ float g_deg[B_ * NN_];
__device__ float g_xa[B_ * NN_ * 17];
__device__ float g_xb[B_ * NN_ * 17];
__device__ float g_vbuf[B_ * NN_];
__device__ unsigned int g_maxbits;

// ---------------- small helpers ----------------
__device__ __forceinline__ float quad_max(float v) {
    v = fmaxf(v, __shfl_xor_sync(0xffffffffu, v, 1));
    v = fmaxf(v, __shfl_xor_sync(0xffffffffu, v, 2));
    return v;
}
__device__ __forceinline__ float quad_sum(float v) {
    v += __shfl_xor_sync(0xffffffffu, v, 1);
    v += __shfl_xor_sync(0xffffffffu, v, 2);
    return v;
}
__device__ __forceinline__ float warp_sum(float v) {
    #pragma unroll
    for (int o = 16; o > 0; o >>= 1) v += __shfl_xor_sync(0xffffffffu, v, o);
    return v;
}
__device__ __forceinline__ float warp_max(float v) {
    #pragma unroll
    for (int o = 16; o > 0; o >>= 1) v = fmaxf(v, __shfl_xor_sync(0xffffffffu, v, o));
    return v;
}

// ---------------- 0: init ----------------
__global__ void k_init() { g_maxbits = 0u; }

// ---------------- 1: fused projection GEMM  H = [x1;x2;e1;e2] @ Wp + bp ----------------
// 4096 x 1024 x 256, tiles 64x64, BK=16, 256 threads, 4x4 microtile
__global__ void k_gemm_proj(const float* __restrict__ x1, const float* __restrict__ x2,
                            const float* __restrict__ e1, const float* __restrict__ e2,
                            const float* __restrict__ Wp, const float* __restrict__ bp) {
    __shared__ float As[16][64];
    __shared__ float Bs[16][64];
    int tid = threadIdx.x;
    int bm = blockIdx.x * 64;
    int bn = blockIdx.y * 64;

    int arow = tid >> 2;            // 0..63
    int acol = (tid & 3) * 4;       // 0,4,8,12
    int gr = bm + arow;
    const float* src; int lr;
    if (gr < 512)       { src = x1; lr = gr; }
    else if (gr < 1024) { src = x2; lr = gr - 512; }
    else if (gr < 2560) { src = e1; lr = gr - 1024; }
    else                { src = e2; lr = gr - 2560; }
    const float* aptr = src + (long)lr * DIN;

    int brow = tid >> 4;            // 0..15
    int bcol = (tid & 15) * 4;      // 0..60

    int ty = tid >> 4, tx = tid & 15;
    float acc[4][4];
    #pragma unroll
    for (int u = 0; u < 4; u++)
        #pragma unroll
        for (int v = 0; v < 4; v++) acc[u][v] = 0.f;

    for (int k0 = 0; k0 < DIN; k0 += 16) {
        float4 av = *(const float4*)(aptr + k0 + acol);
        float4 bv = *(const float4*)(Wp + (long)(k0 + brow) * DP + bn + bcol);
        As[acol + 0][arow] = av.x;
        As[acol + 1][arow] = av.y;
        As[acol + 2][arow] = av.z;
        As[acol + 3][arow] = av.w;
        *(float4*)&Bs[brow][bcol] = bv;
        __syncthreads();
        #pragma unroll
        for (int k = 0; k < 16; k++) {
            float4 a = *(const float4*)&As[k][ty * 4];
            float4 b = *(const float4*)&Bs[k][tx * 4];
            float ar[4] = {a.x, a.y, a.z, a.w};
            float br[4] = {b.x, b.y, b.z, b.w};
            #pragma unroll
            for (int u = 0; u < 4; u++)
                #pragma unroll
                for (int v = 0; v < 4; v++)
                    acc[u][v] = fmaf(ar[u], br[v], acc[u][v]);
        }
        __syncthreads();
    }
    float4 bpv = *(const float4*)(bp + bn + tx * 4);
    #pragma unroll
    for (int u = 0; u < 4; u++) {
        float4 o;
        o.x = acc[u][0] + bpv.x; o.y = acc[u][1] + bpv.y;
        o.z = acc[u][2] + bpv.z; o.w = acc[u][3] + bpv.w;
        *(float4*)&g_H[(long)(bm + ty * 4 + u) * DP + bn + tx * 4] = o;
    }
}

// ---------------- 2: per-segment per-column mean/var ----------------
__global__ void k_stats() {
    const int segs[5] = {0, 512, 1024, 2560, 4096};
    int seg = blockIdx.x >> 3;
    int cg  = blockIdx.x & 7;
    int col = cg * 32 + (threadIdx.x & 31);
    int rt  = threadIdx.x >> 5;   // 0..7
    int r0 = segs[seg], r1 = segs[seg + 1];
    float s = 0.f, q = 0.f;
    for (int r = r0 + rt; r < r1; r += 8) {
        float v = g_H[(long)r * DP + col];
        s += v; q += v * v;
    }
    __shared__ float ss[8][32], sq[8][32];
    ss[rt][threadIdx.x & 31] = s;
    sq[rt][threadIdx.x & 31] = q;
    __syncthreads();
    if (rt == 0) {
        for (int i = 1; i < 8; i++) { s += ss[i][threadIdx.x & 31]; q += sq[i][threadIdx.x & 31]; }
        float cnt = (float)(r1 - r0);
        float mu = s / cnt;
        g_mu[seg * DP + col]  = mu;
        g_var[seg * DP + col] = q / cnt - mu * mu;
    }
}

// ---------------- 3: BN + relu + row L2 normalize (in place) ----------------
__global__ void k_bn_l2(const float* __restrict__ gamma, const float* __restrict__ beta) {
    int row = blockIdx.x;
    int c = threadIdx.x;
    int seg = row < 512 ? 0 : row < 1024 ? 1 : row < 2560 ? 2 : 3;
    float v = g_H[(long)row * DP + c];
    v = (v - g_mu[seg * DP + c]) * rsqrtf(g_var[seg * DP + c] + 1e-5f) * gamma[c] + beta[c];
    v = fmaxf(v, 0.f);
    float sq = v * v;
    sq = warp_sum(sq);
    __shared__ float red[8];
    if ((c & 31) == 0) red[c >> 5] = sq;
    __syncthreads();
    float tot = 0.f;
    #pragma unroll
    for (int i = 0; i < 8; i++) tot += red[i];
    float inv = 1.0f / fmaxf(sqrtf(tot), 1e-12f);
    g_H[(long)row * DP + c] = v * inv;
}

// ---------------- 4: batched NT gemm (Kp and Ke) ----------------
// C[b][i][j] = scale * sum_d A[offA + b*Ma + i][d] * Bm[offB + b*Mb + j][d]
__global__ void k_nt(int offA, int offB, int Ma, int Mb, float scale, float* __restrict__ out) {
    __shared__ float As[32][33];
    __shared__ float Bs[32][33];
    int b = blockIdx.z;
    const float* A  = g_H + (long)(offA + b * Ma) * DP;
    const float* Bm = g_H + (long)(offB + b * Mb) * DP;
    int i0 = blockIdx.x * 32, j0 = blockIdx.y * 32;
    int tid = threadIdx.x;
    int lr = tid >> 3, lc = (tid & 7) * 4;
    int ty = tid >> 4, tx = tid & 15;
    float a00 = 0.f, a01 = 0.f, a10 = 0.f, a11 = 0.f;
    for (int k0 = 0; k0 < DP; k0 += 32) {
        float4 av = *(const float4*)(A  + (long)(i0 + lr) * DP + k0 + lc);
        float4 bv = *(const float4*)(Bm + (long)(j0 + lr) * DP + k0 + lc);
        As[lr][lc] = av.x; As[lr][lc+1] = av.y; As[lr][lc+2] = av.z; As[lr][lc+3] = av.w;
        Bs[lr][lc] = bv.x; Bs[lr][lc+1] = bv.y; Bs[lr][lc+2] = bv.z; Bs[lr][lc+3] = bv.w;
        __syncthreads();
        #pragma unroll
        for (int k = 0; k < 32; k++) {
            float x0 = As[ty*2][k], x1 = As[ty*2+1][k];
            float y0 = Bs[tx*2][k], y1 = Bs[tx*2+1][k];
            a00 = fmaf(x0, y0, a00); a01 = fmaf(x0, y1, a01);
            a10 = fmaf(x1, y0, a10); a11 = fmaf(x1, y1, a11);
        }
        __syncthreads();
    }
    long ob = (long)b * Ma * Mb;
    out[ob + (long)(i0 + ty*2    ) * Mb + j0 + tx*2    ] = a00 * scale;
    out[ob + (long)(i0 + ty*2    ) * Mb + j0 + tx*2 + 1] = a01 * scale;
    out[ob + (long)(i0 + ty*2 + 1) * Mb + j0 + tx*2    ] = a10 * scale;
    out[ob + (long)(i0 + ty*2 + 1) * Mb + j0 + tx*2 + 1] = a11 * scale;
}

// ---------------- 5: deterministic adjacency lists ----------------
__global__ void k_lists(const int* __restrict__ s1, const int* __restrict__ s2) {
    int t = blockIdx.x * blockDim.x + threadIdx.x;
    if (t >= B_ * N_) return;
    int b = t >> 6, a = t & 63;
    int c = 0;
    for (int e = 0; e < E_; e++) if (s1[b * E_ + e] == a) g_idx1[t * E_ + c++] = e;
    g_cnt1[t] = c;
    c = 0;
    for (int e = 0; e < E_; e++) if (s2[b * E_ + e] == a) g_idx2[t * E_ + c++] = e;
    g_cnt2[t] = c;
}

// ---------------- 6: deg per row (deduped column sums) + x0 init ----------------
__global__ void k_deg(const int* __restrict__ dst1, const int* __restrict__ dst2) {
    int gid = blockIdx.x * blockDim.x + threadIdx.x;
    if (gid >= B_ * NN_) return;
    int b = gid >> 12, r = gid & 4095;
    int alpha = r >> 6, a = r & 63;
    const int* I = &g_idx1[(b * N_ + a) * E_];     int nI = g_cnt1[b * N_ + a];
    const int* J = &g_idx2[(b * N_ + alpha) * E_]; int nJ = g_cnt2[b * N_ + alpha];
    const float* Keb = g_Ke + (long)b * E_ * E_;
    const int* d1 = dst1 + b * E_;
    const int* d2 = dst2 + b * E_;

    int cnt = 0;
    float ti[E_];  // per-i partial sums for current beta (only first nI used)
    for (int jj = 0; jj < nJ; jj++) {
        int bet = d2[J[jj]];
        bool seen = false;
        for (int j2 = 0; j2 < jj; j2++) if (d2[J[j2]] == bet) { seen = true; break; }
        if (seen) continue;
        // t_i = sum over j in J with d2==bet of Ke[i][j]
        for (int ii = 0; ii < nI; ii++) {
            int i = I[ii];
            float s = 0.f;
            for (int j3 = 0; j3 < nJ; j3++) {
                int j = J[j3];
                if (d2[j] == bet) s += Keb[i * E_ + j];
            }
            ti[ii] = s;
        }
        // distinct b' values among d1[I]
        for (int ii = 0; ii < nI; ii++) {
            int bprime = d1[I[ii]];
            bool seen2 = false;
            for (int i2 = 0; i2 < ii; i2++) if (d1[I[i2]] == bprime) { seen2 = true; break; }
            if (seen2) continue;
            if (bprime == a && bet == alpha) continue;  // diagonal: overwritten by Kp
            float sum = 0.f;
            for (int i3 = 0; i3 < nI; i3++) if (d1[I[i3]] == bprime) sum += ti[i3];
            if (sum > 0.f) cnt++;
        }
    }
    float dv = g_Kp[(long)b * NN_ + a * N_ + alpha];
    if (dv > 0.f) cnt++;
    g_deg[gid] = fmaxf((float)cnt, 1.0f);
    g_xa[(long)gid * 17] = dv;   // x0 (channel 0) = Kp[a][alpha]
}

// ---------------- 7: GNN layer (warp per row) ----------------
template <int CIN>
__global__ void k_layer(const float* __restrict__ xin, float* __restrict__ xout,
                        const float* __restrict__ W, const float* __restrict__ bb,
                        const float* __restrict__ S, const float* __restrict__ cc,
                        const int* __restrict__ dst1, const int* __restrict__ dst2) {
    int wid = (blockIdx.x * blockDim.x + threadIdx.x) >> 5;
    int lane = threadIdx.x & 31;
    if (wid >= B_ * NN_) return;
    int b = wid >> 12, r = wid & 4095;
    int alpha = r >> 6, a = r & 63;
    const int* I = &g_idx1[(b * N_ + a) * E_];     int nI = g_cnt1[b * N_ + a];
    const int* J = &g_idx2[(b * N_ + alpha) * E_]; int nJ = g_cnt2[b * N_ + alpha];
    const float* Keb = g_Ke + (long)b * E_ * E_;
    const int* d1 = dst1 + b * E_;
    const int* d2 = dst2 + b * E_;

    float acc[CIN];
    #pragma unroll
    for (int ch = 0; ch < CIN; ch++) acc[ch] = 0.f;

    int nP = nI * nJ;
    for (int p = lane; p < nP; p += 32) {
        int ii = p / nJ, jj = p - ii * nJ;
        int i = I[ii], j = J[jj];
        int col = d2[j] * N_ + d1[i];
        if (col == r) continue;
        float val = Keb[i * E_ + j];
        const float* xc = xin + ((long)b * NN_ + col) * 17;
        #pragma unroll
        for (int ch = 0; ch < CIN; ch++) acc[ch] = fmaf(val, xc[ch], acc[ch]);
    }
    #pragma unroll
    for (int ch = 0; ch < CIN; ch++) acc[ch] = warp_sum(acc[ch]);

    float dval = g_Kp[(long)b * NN_ + a * N_ + alpha];
    float invd = 1.0f / g_deg[wid];
    const float* xr = xin + ((long)b * NN_ + r) * 17;
    float msg[CIN];
    #pragma unroll
    for (int ch = 0; ch < CIN; ch++) msg[ch] = (acc[ch] + dval * xr[ch]) * invd;

    float hf = 0.f;
    if (lane < F_) {
        hf = bb[lane];
        #pragma unroll
        for (int ch = 0; ch < CIN; ch++) hf = fmaf(msg[ch], W[ch * F_ + lane], hf);
        hf = fmaxf(hf, 0.f);
        xout[((long)b * NN_ + r) * 17 + lane] = hf;
    }
    float contrib = (lane < F_) ? hf * S[lane] : 0.f;
    contrib = warp_sum(contrib);
    if (lane == 0) g_vbuf[wid] = contrib + cc[0];
}

// ---------------- 8: mid Sinkhorn (64x64, 10 iters), writes channel 16 ----------------
__global__ void k_sinkhorn_mid(float* __restrict__ xout) {
    __shared__ float M[64 * 65];
    int b = blockIdx.x, tid = threadIdx.x;
    for (int idx = tid; idx < NN_; idx += 256) {
        int q = idx >> 6, p = idx & 63;
        M[p * 65 + q] = g_vbuf[b * NN_ + idx] * (1.0f / TAU);
    }
    __syncthreads();
    int p = tid >> 2, s = tid & 3;
    for (int it = 0; it < 10; it++) {
        // rows (axis=2)
        float m = -3.0e38f;
        for (int q = s; q < 64; q += 4) m = fmaxf(m, M[p * 65 + q]);
        m = quad_max(m);
        float sum = 0.f;
        for (int q = s; q < 64; q += 4) sum += expf(M[p * 65 + q] - m);
        sum = quad_sum(sum);
        float lse = m + logf(sum);
        for (int q = s; q < 64; q += 4) M[p * 65 + q] -= lse;
        __syncthreads();
        // cols (axis=1)
        m = -3.0e38f;
        for (int rr = s; rr < 64; rr += 4) m = fmaxf(m, M[rr * 65 + p]);
        m = quad_max(m);
        sum = 0.f;
        for (int rr = s; rr < 64; rr += 4) sum += expf(M[rr * 65 + p] - m);
        sum = quad_sum(sum);
        lse = m + logf(sum);
        for (int rr = s; rr < 64; rr += 4) M[rr * 65 + p] -= lse;
        __syncthreads();
    }
    for (int idx = tid; idx < NN_; idx += 256) {
        int q = idx >> 6, p2 = idx & 63;
        xout[((long)b * NN_ + idx) * 17 + 16] = expf(M[p2 * 65 + q]);
    }
}

// ---------------- 9: final 65x65 binned Sinkhorn + out + global max ----------------
__global__ void k_final(const float* __restrict__ x, const float* __restrict__ Wc,
                        const float* __restrict__ bc, const float* __restrict__ binp,
                        float* __restrict__ out) {
    __shared__ float M[65 * 66];
    __shared__ float wl[17];
    __shared__ float wmax[9];
    int b = blockIdx.x, tid = threadIdx.x;
    if (tid < 17) wl[tid] = Wc[tid];
    __syncthreads();
    float bcv = bc[0];
    for (int idx = tid; idx < NN_; idx += 288) {
        const float* xr = x + ((long)b * NN_ + idx) * 17;
        float v = bcv;
        #pragma unroll
        for (int ch = 0; ch < 17; ch++) v = fmaf(xr[ch], wl[ch], v);
        int q = idx >> 6, p = idx & 63;
        M[p * 66 + q] = v;
    }
    if (tid < 65) { float bv = binp[0]; M[64 * 66 + tid] = bv; M[tid * 66 + 64] = bv; }
    __syncthreads();
    int p = tid >> 2, s = tid & 3;
    bool act = p < 65;
    for (int it = 0; it < 10; it++) {
        float m = -3.0e38f, sum = 0.f, lse;
        if (act) for (int q = s; q < 65; q += 4) m = fmaxf(m, M[p * 66 + q]);
        m = quad_max(m);
        if (act) for (int q = s; q < 65; q += 4) sum += expf(M[p * 66 + q] - m);
        sum = quad_sum(sum);
        lse = m + logf(sum);
        if (act) for (int q = s; q < 65; q += 4) M[p * 66 + q] -= lse;
        __syncthreads();
        m = -3.0e38f; sum = 0.f;
        if (act) for (int rr = s; rr < 65; rr += 4) m = fmaxf(m, M[rr * 66 + p]);
        m = quad_max(m);
        if (act) for (int rr = s; rr < 65; rr += 4) sum += expf(M[rr * 66 + p] - m);
        sum = quad_sum(sum);
        lse = m + logf(sum);
        if (act) for (int rr = s; rr < 65; rr += 4) M[rr * 66 + p] -= lse;
        __syncthreads();
    }
    float lmax = 0.f;
    for (int oidx = tid; oidx < NN_; oidx += 288) {
        int pp = oidx >> 6, qq = oidx & 63;
        float val = expf(M[pp * 66 + qq]);
        out[(long)b * NN_ + oidx] = val;
        lmax = fmaxf(lmax, val);
    }
    lmax = warp_max(lmax);
    if ((tid & 31) == 0) wmax[tid >> 5] = lmax;
    __syncthreads();
    if (tid == 0) {
        float bm = 0.f;
        #pragma unroll
        for (int i = 0; i < 9; i++) bm = fmaxf(bm, wmax[i]);
        atomicMax(&g_maxbits, __float_as_uint(bm));   // all values > 0
    }
}

// ---------------- 10: scale by global max ----------------
__global__ void k_scale(float* __restrict__ out) {
    int i = blockIdx.x * blockDim.x + threadIdx.x;
    if (i < B_ * NN_) out[i] = out[i] / __uint_as_float(g_maxbits);
}

// ---------------- launch ----------------
extern "C" void kernel_launch(void* const* d_in, const int* in_sizes, int n_in,
                              void* d_out, int out_size) {
    (void)in_sizes; (void)n_in; (void)out_size;
    const float* x1    = (const float*)d_in[0];
    const float* x2    = (const float*)d_in[1];
    const float* e1    = (const float*)d_in[2];
    const float* e2    = (const float*)d_in[3];
    const float* Wp    = (const float*)d_in[4];
    const float* bp    = (const float*)d_in[5];
    const float* gamma = (const float*)d_in[6];
    const float* beta  = (const float*)d_in[7];
    const float* W0 = (const float*)d_in[8];
    const float* b0 = (const float*)d_in[9];
    const float* S0 = (const float*)d_in[10];
    const float* c0 = (const float*)d_in[11];
    const float* W1 = (const float*)d_in[12];
    const float* b1 = (const float*)d_in[13];
    const float* S1 = (const float*)d_in[14];
    const float* c1 = (const float*)d_in[15];
    const float* W2 = (const float*)d_in[16];
    const float* b2 = (const float*)d_in[17];
    const float* S2 = (const float*)d_in[18];
    const float* c2 = (const float*)d_in[19];
    const float* Wc = (const float*)d_in[20];
    const float* bc = (const float*)d_in[21];
    const float* binv = (const float*)d_in[22];
    const int* src1 = (const int*)d_in[23];
    const int* dst1 = (const int*)d_in[24];
    const int* src2 = (const int*)d_in[25];
    const int* dst2 = (const int*)d_in[26];
    float* out = (float*)d_out;

    float* g_Kp_p; cudaGetSymbolAddress((void**)&g_Kp_p, g_Kp);
    float* g_Ke_p; cudaGetSymbolAddress((void**)&g_Ke_p, g_Ke);
    float* g_xa_p; cudaGetSymbolAddress((void**)&g_xa_p, g_xa);
    float* g_xb_p; cudaGetSymbolAddress((void**)&g_xb_p, g_xb);

    k_init<<<1, 1>>>();
    k_gemm_proj<<<dim3(64, 4), 256>>>(x1, x2, e1, e2, Wp, bp);
    k_stats<<<32, 256>>>();
    k_bn_l2<<<ROWS_TOT, 256>>>(gamma, beta);
    // Kp: p1 rows [0,512), p2 rows [512,1024), Ma=Mb=64
    k_nt<<<dim3(2, 2, B_), 256>>>(0, 512, N_, N_, 1.0f, g_Kp_p);
    // Ke: q1 rows [1024,2560), q2 rows [2560,4096), Ma=Mb=192, scale 0.5
    k_nt<<<dim3(6, 6, B_), 256>>>(1024, 2560, E_, E_, 0.5f, g_Ke_p);
    k_lists<<<2, 256>>>(src1, src2);
    k_deg<<<128, 256>>>(dst1, dst2);

    // layer 0: CIN=1, xa -> xb
    k_layer<1><<<4096, 256>>>(g_xa_p, g_xb_p, W0, b0, S0, c0, dst1, dst2);
    k_sinkhorn_mid<<<B_, 256>>>(g_xb_p);
    // layer 1: CIN=17, xb -> xa
    k_layer<17><<<4096, 256>>>(g_xb_p, g_xa_p, W1, b1, S1, c1, dst1, dst2);
    k_sinkhorn_mid<<<B_, 256>>>(g_xa_p);
    // layer 2: CIN=17, xa -> xb
    k_layer<17><<<4096, 256>>>(g_xa_p, g_xb_p, W2, b2, S2, c2, dst1, dst2);
    k_sinkhorn_mid<<<B_, 256>>>(g_xb_p);

    k_final<<<B_, 288>>>(g_xb_p, Wc, bc, binv, out);
    k_scale<<<32, 1024>>>(out);
}

// round 5
// speedup vs baseline: 1.4510x; 1.4510x over previous
#include <cuda_runtime.h>
#include <math.h>

// ---------------- problem constants ----------------
#define B_   8
#define N_   64
#define E_   192
#define DIN  1024
#define DP   256
#define F_   16
#define NN_  4096
#define ROWS_TOT 4096   // 512 + 512 + 1536 + 1536
#define CAP  256        // max deduped CSR entries per row
#define FULLM 0xffffffffu

// ---------------- device scratch ----------------
__device__ float g_P0[ROWS_TOT * DP];
__device__ float g_P1[ROWS_TOT * DP];
__device__ float g_H[ROWS_TOT * DP];
__device__ float g_mu[4 * DP];
__device__ float g_var[4 * DP];
__device__ float g_Kp[B_ * N_ * N_];
__device__ float g_Ke[B_ * E_ * E_];
__device__ int   g_cnt1[B_ * N_], g_cnt2[B_ * N_];
__device__ int   g_idx1[B_ * N_ * E_], g_idx2[B_ * N_ * E_];
__device__ float g_deg[B_ * NN_];
__device__ unsigned short g_ccol[B_ * NN_ * CAP];
__device__ float g_cval[B_ * NN_ * CAP];
__device__ int   g_ccnt[B_ * NN_];
__device__ float g_xa[B_ * NN_ * 20];
__device__ float g_xb[B_ * NN_ * 20];
__device__ float g_vbuf[B_ * NN_];
__device__ unsigned int g_maxbits;

// ---------------- helpers ----------------
__device__ __forceinline__ float oct_max(float v) {
    v = fmaxf(v, __shfl_xor_sync(FULLM, v, 1));
    v = fmaxf(v, __shfl_xor_sync(FULLM, v, 2));
    v = fmaxf(v, __shfl_xor_sync(FULLM, v, 4));
    return v;
}
__device__ __forceinline__ float oct_sum(float v) {
    v += __shfl_xor_sync(FULLM, v, 1);
    v += __shfl_xor_sync(FULLM, v, 2);
    v += __shfl_xor_sync(FULLM, v, 4);
    return v;
}
__device__ __forceinline__ float warp_sum(float v) {
    #pragma unroll
    for (int o = 16; o > 0; o >>= 1) v += __shfl_xor_sync(FULLM, v, o);
    return v;
}
__device__ __forceinline__ float warp_max(float v) {
    #pragma unroll
    for (int o = 16; o > 0; o >>= 1) v = fmaxf(v, __shfl_xor_sync(FULLM, v, o));
    return v;
}

__global__ void k_init() { g_maxbits = 0u; }

// ---------------- 1: projection GEMM, 128x128 tile, 8x8 micro, split-K=2, double buffered ----------------
// As row stride = 132 floats (528B, multiple of 16B) so float4 reads stay aligned.
__global__ void __launch_bounds__(256) k_gemm(const float* __restrict__ x1, const float* __restrict__ x2,
                                              const float* __restrict__ e1, const float* __restrict__ e2,
                                              const float* __restrict__ Wp) {
    __shared__ float As[2][16][132];
    __shared__ float Bs[2][16][128];
    int tid = threadIdx.x;
    int bm = blockIdx.x * 128, bn = blockIdx.y * 128;
    int kbase = blockIdx.z * 512;

    // A loader: row = tid>>1, k sub = (tid&1)*8
    int arow = tid >> 1;
    int akb = (tid & 1) * 8;
    int gr = bm + arow;
    const float* src; int lr;
    if (gr < 512)       { src = x1; lr = gr; }
    else if (gr < 1024) { src = x2; lr = gr - 512; }
    else if (gr < 2560) { src = e1; lr = gr - 1024; }
    else                { src = e2; lr = gr - 2560; }
    const float* aptr = src + (long)lr * DIN + kbase + akb;

    // B loader: k row = tid>>4, n sub = (tid&15)*8
    int bkb = tid >> 4;
    int bnb = (tid & 15) * 8;
    const float* bptr = Wp + (long)(kbase + bkb) * DP + bn + bnb;

    int ty = tid >> 4, tx = tid & 15;
    float acc[8][8];
    #pragma unroll
    for (int u = 0; u < 8; u++)
        #pragma unroll
        for (int v = 0; v < 8; v++) acc[u][v] = 0.f;

    float4 a0 = *(const float4*)(aptr);
    float4 a1 = *(const float4*)(aptr + 4);
    float4 b0 = *(const float4*)(bptr);
    float4 b1 = *(const float4*)(bptr + 4);
    As[0][akb + 0][arow] = a0.x; As[0][akb + 1][arow] = a0.y;
    As[0][akb + 2][arow] = a0.z; As[0][akb + 3][arow] = a0.w;
    As[0][akb + 4][arow] = a1.x; As[0][akb + 5][arow] = a1.y;
    As[0][akb + 6][arow] = a1.z; As[0][akb + 7][arow] = a1.w;
    *(float4*)&Bs[0][bkb][bnb]     = b0;
    *(float4*)&Bs[0][bkb][bnb + 4] = b1;
    __syncthreads();

    int buf = 0;
    for (int it = 0; it < 32; it++) {
        if (it < 31) {
            a0 = *(const float4*)(aptr + (it + 1) * 16);
            a1 = *(const float4*)(aptr + (it + 1) * 16 + 4);
            b0 = *(const float4*)(bptr + (long)(it + 1) * 16 * DP);
            b1 = *(const float4*)(bptr + (long)(it + 1) * 16 * DP + 4);
        }
        #pragma unroll
        for (int kk = 0; kk < 16; kk++) {
            float4 av0 = *(const float4*)&As[buf][kk][ty * 8];
            float4 av1 = *(const float4*)&As[buf][kk][ty * 8 + 4];
            float4 bv0 = *(const float4*)&Bs[buf][kk][tx * 8];
            float4 bv1 = *(const float4*)&Bs[buf][kk][tx * 8 + 4];
            float ar[8] = {av0.x, av0.y, av0.z, av0.w, av1.x, av1.y, av1.z, av1.w};
            float br[8] = {bv0.x, bv0.y, bv0.z, bv0.w, bv1.x, bv1.y, bv1.z, bv1.w};
            #pragma unroll
            for (int u = 0; u < 8; u++)
                #pragma unroll
                for (int v = 0; v < 8; v++)
                    acc[u][v] = fmaf(ar[u], br[v], acc[u][v]);
        }
        if (it < 31) {
            int nb = buf ^ 1;
            As[nb][akb + 0][arow] = a0.x; As[nb][akb + 1][arow] = a0.y;
            As[nb][akb + 2][arow] = a0.z; As[nb][akb + 3][arow] = a0.w;
            As[nb][akb + 4][arow] = a1.x; As[nb][akb + 5][arow] = a1.y;
            As[nb][akb + 6][arow] = a1.z; As[nb][akb + 7][arow] = a1.w;
            *(float4*)&Bs[nb][bkb][bnb]     = b0;
            *(float4*)&Bs[nb][bkb][bnb + 4] = b1;
            __syncthreads();
            buf = nb;
        }
    }
    float* outp = blockIdx.z ? g_P1 : g_P0;
    #pragma unroll
    for (int u = 0; u < 8; u++) {
        float4 o0 = {acc[u][0], acc[u][1], acc[u][2], acc[u][3]};
        float4 o1 = {acc[u][4], acc[u][5], acc[u][6], acc[u][7]};
        long ro = (long)(bm + ty * 8 + u) * DP + bn + tx * 8;
        *(float4*)&outp[ro]     = o0;
        *(float4*)&outp[ro + 4] = o1;
    }
}

// ---------------- 2: combine partials + bias, write H, segment stats ----------------
__global__ void k_statsc(const float* __restrict__ bp) {
    const int segs[5] = {0, 512, 1024, 2560, 4096};
    int seg = blockIdx.x >> 3;
    int cg  = blockIdx.x & 7;
    int col = cg * 32 + (threadIdx.x & 31);
    int rt  = threadIdx.x >> 5;
    int r0 = segs[seg], r1 = segs[seg + 1];
    float bpc = bp[col];
    float s = 0.f, q = 0.f;
    for (int r = r0 + rt; r < r1; r += 8) {
        long i = (long)r * DP + col;
        float h = g_P0[i] + g_P1[i] + bpc;
        g_H[i] = h;
        s += h; q += h * h;
    }
    __shared__ float ss[8][32], sq[8][32];
    ss[rt][threadIdx.x & 31] = s;
    sq[rt][threadIdx.x & 31] = q;
    __syncthreads();
    if (rt == 0) {
        for (int i = 1; i < 8; i++) { s += ss[i][threadIdx.x & 31]; q += sq[i][threadIdx.x & 31]; }
        float cnt = (float)(r1 - r0);
        float mu = s / cnt;
        g_mu[seg * DP + col]  = mu;
        g_var[seg * DP + col] = q / cnt - mu * mu;
    }
}

// ---------------- 3: BN + relu + L2, warp per row ----------------
__global__ void k_bn(const float* __restrict__ gamma, const float* __restrict__ beta) {
    int w = threadIdx.x >> 5, lane = threadIdx.x & 31;
    int row = blockIdx.x * 8 + w;
    int seg = row < 512 ? 0 : row < 1024 ? 1 : row < 2560 ? 2 : 3;
    int c0 = lane * 4, c1 = 128 + lane * 4;
    long rb = (long)row * DP;
    float4 v0 = *(const float4*)&g_H[rb + c0];
    float4 v1 = *(const float4*)&g_H[rb + c1];
    float4 m0 = *(const float4*)&g_mu[seg * DP + c0];
    float4 m1 = *(const float4*)&g_mu[seg * DP + c1];
    float4 a0 = *(const float4*)&g_var[seg * DP + c0];
    float4 a1 = *(const float4*)&g_var[seg * DP + c1];
    float4 ga0 = *(const float4*)&gamma[c0];
    float4 ga1 = *(const float4*)&gamma[c1];
    float4 be0 = *(const float4*)&beta[c0];
    float4 be1 = *(const float4*)&beta[c1];
    float t[8];
    t[0] = (v0.x - m0.x) * rsqrtf(a0.x + 1e-5f) * ga0.x + be0.x;
    t[1] = (v0.y - m0.y) * rsqrtf(a0.y + 1e-5f) * ga0.y + be0.y;
    t[2] = (v0.z - m0.z) * rsqrtf(a0.z + 1e-5f) * ga0.z + be0.z;
    t[3] = (v0.w - m0.w) * rsqrtf(a0.w + 1e-5f) * ga0.w + be0.w;
    t[4] = (v1.x - m1.x) * rsqrtf(a1.x + 1e-5f) * ga1.x + be1.x;
    t[5] = (v1.y - m1.y) * rsqrtf(a1.y + 1e-5f) * ga1.y + be1.y;
    t[6] = (v1.z - m1.z) * rsqrtf(a1.z + 1e-5f) * ga1.z + be1.z;
    t[7] = (v1.w - m1.w) * rsqrtf(a1.w + 1e-5f) * ga1.w + be1.w;
    float sq = 0.f;
    #pragma unroll
    for (int i = 0; i < 8; i++) { t[i] = fmaxf(t[i], 0.f); sq = fmaf(t[i], t[i], sq); }
    sq = warp_sum(sq);
    float inv = 1.0f / fmaxf(sqrtf(sq), 1e-12f);
    float4 o0 = {t[0] * inv, t[1] * inv, t[2] * inv, t[3] * inv};
    float4 o1 = {t[4] * inv, t[5] * inv, t[6] * inv, t[7] * inv};
    *(float4*)&g_H[rb + c0] = o0;
    *(float4*)&g_H[rb + c1] = o1;
}

// ---------------- 4: batched NT gemm (Kp, Ke) ----------------
__global__ void k_nt(int offA, int offB, int Ma, int Mb, float scale, float* __restrict__ out) {
    __shared__ float As[32][33];
    __shared__ float Bs[32][33];
    int b = blockIdx.z;
    const float* A  = g_H + (long)(offA + b * Ma) * DP;
    const float* Bm = g_H + (long)(offB + b * Mb) * DP;
    int i0 = blockIdx.x * 32, j0 = blockIdx.y * 32;
    int tid = threadIdx.x;
    int lr = tid >> 3, lc = (tid & 7) * 4;
    int ty = tid >> 4, tx = tid & 15;
    float a00 = 0.f, a01 = 0.f, a10 = 0.f, a11 = 0.f;
    for (int k0 = 0; k0 < DP; k0 += 32) {
        float4 av = *(const float4*)(A  + (long)(i0 + lr) * DP + k0 + lc);
        float4 bv = *(const float4*)(Bm + (long)(j0 + lr) * DP + k0 + lc);
        As[lr][lc] = av.x; As[lr][lc+1] = av.y; As[lr][lc+2] = av.z; As[lr][lc+3] = av.w;
        Bs[lr][lc] = bv.x; Bs[lr][lc+1] = bv.y; Bs[lr][lc+2] = bv.z; Bs[lr][lc+3] = bv.w;
        __syncthreads();
        #pragma unroll
        for (int k = 0; k < 32; k++) {
            float x0 = As[ty*2][k], x1 = As[ty*2+1][k];
            float y0 = Bs[tx*2][k], y1 = Bs[tx*2+1][k];
            a00 = fmaf(x0, y0, a00); a01 = fmaf(x0, y1, a01);
            a10 = fmaf(x1, y0, a10); a11 = fmaf(x1, y1, a11);
        }
        __syncthreads();
    }
    long ob = (long)b * Ma * Mb;
    out[ob + (long)(i0 + ty*2    ) * Mb + j0 + tx*2    ] = a00 * scale;
    out[ob + (long)(i0 + ty*2    ) * Mb + j0 + tx*2 + 1] = a01 * scale;
    out[ob + (long)(i0 + ty*2 + 1) * Mb + j0 + tx*2    ] = a10 * scale;
    out[ob + (long)(i0 + ty*2 + 1) * Mb + j0 + tx*2 + 1] = a11 * scale;
}

// ---------------- 5: adjacency lists ----------------
__global__ void k_lists(const int* __restrict__ s1, const int* __restrict__ s2) {
    int t = blockIdx.x * blockDim.x + threadIdx.x;
    if (t >= B_ * N_) return;
    int b = t >> 6, a = t & 63;
    int c = 0;
    for (int e = 0; e < E_; e++) if (s1[b * E_ + e] == a) g_idx1[t * E_ + c++] = e;
    g_cnt1[t] = c;
    c = 0;
    for (int e = 0; e < E_; e++) if (s2[b * E_ + e] == a) g_idx2[t * E_ + c++] = e;
    g_cnt2[t] = c;
}

// ---------------- 6: build deduped CSR + deg + x0, warp per row ----------------
__global__ void __launch_bounds__(256) k_build(const int* __restrict__ dst1, const int* __restrict__ dst2) {
    __shared__ int eI[8][32], eJ[8][32];
    __shared__ unsigned mA[8][32], mB[8][32];
    __shared__ int vA[8][32], vB[8][32];
    int w = threadIdx.x >> 5, lane = threadIdx.x & 31;
    int gid = blockIdx.x * 8 + w;          // row id, 0..32767
    int b = gid >> 12, r = gid & 4095;
    int alpha = r >> 6, a = r & 63;

    int nI = g_cnt1[b * N_ + a];      if (nI > 32) nI = 32;
    int nJ = g_cnt2[b * N_ + alpha];  if (nJ > 32) nJ = 32;

    // side A: edges of graph1 with s1==a, key = d1
    int keyA = 4096 + lane;
    if (lane < nI) {
        int e = g_idx1[(b * N_ + a) * E_ + lane];
        eI[w][lane] = e;
        keyA = dst1[b * E_ + e];
    }
    unsigned maskA = __match_any_sync(FULLM, keyA);
    bool leadA = ((maskA & ((1u << lane) - 1u)) == 0u) && (lane < nI);
    unsigned balA = __ballot_sync(FULLM, leadA);
    int ua = __popc(balA);
    if (leadA) {
        int rk = __popc(balA & ((1u << lane) - 1u));
        vA[w][rk] = keyA; mA[w][rk] = maskA;
    }
    // side B: edges of graph2 with s2==alpha, key = d2
    int keyB = 8192 + lane;
    if (lane < nJ) {
        int e = g_idx2[(b * N_ + alpha) * E_ + lane];
        eJ[w][lane] = e;
        keyB = dst2[b * E_ + e];
    }
    unsigned maskB = __match_any_sync(FULLM, keyB);
    bool leadB = ((maskB & ((1u << lane) - 1u)) == 0u) && (lane < nJ);
    unsigned balB = __ballot_sync(FULLM, leadB);
    int ub = __popc(balB);
    if (leadB) {
        int rk = __popc(balB & ((1u << lane) - 1u));
        vB[w][rk] = keyB; mB[w][rk] = maskB;
    }
    __syncwarp();

    int diagA = -1, diagB = -1;
    for (int t = 0; t < ua; t++) if (vA[w][t] == a) diagA = t;
    for (int t = 0; t < ub; t++) if (vB[w][t] == alpha) diagB = t;
    int diagIdx = (diagA >= 0 && diagB >= 0) ? diagA * ub + diagB : -1;

    const float* Keb = g_Ke + (long)b * E_ * E_;
    int cells = ua * ub;
    long rowbase = (long)gid * CAP;
    int cnt = 0;
    for (int c0 = 0; c0 < cells; c0 += 32) {
        int c = c0 + lane;
        bool activ = (c < cells) && (c != diagIdx);
        float s = 0.f;
        if (activ) {
            int ia = c / ub, ib = c - ia * ub;
            unsigned ma = mA[w][ia];
            unsigned mb0 = mB[w][ib];
            for (unsigned m = ma; m; m &= m - 1) {
                int li = __ffs(m) - 1;
                const float* krow = Keb + eI[w][li] * E_;
                for (unsigned mm = mb0; mm; mm &= mm - 1)
                    s += krow[eJ[w][__ffs(mm) - 1]];
            }
            int pos = c - ((diagIdx >= 0 && c > diagIdx) ? 1 : 0);
            if (pos < CAP) {
                g_ccol[rowbase + pos] = (unsigned short)(vB[w][ib] * N_ + vA[w][ia]);
                g_cval[rowbase + pos] = s;
            }
        }
        unsigned bal = __ballot_sync(FULLM, activ && (s > 0.f));
        cnt += __popc(bal);
    }
    if (lane == 0) {
        int nent = cells - (diagIdx >= 0 ? 1 : 0);
        g_ccnt[gid] = nent < CAP ? nent : CAP;
        float dv = g_Kp[(long)b * NN_ + a * N_ + alpha];
        float deg = (float)(cnt + (dv > 0.f ? 1 : 0));
        g_deg[gid] = fmaxf(deg, 1.0f);
        g_xa[(long)gid * 20] = dv;
    }
}

// ---------------- 7: GNN layer, thread per row, CSR ----------------
template <int CIN>
__global__ void __launch_bounds__(256) k_layer(const float* __restrict__ xin, float* __restrict__ xout,
                        const float* __restrict__ W, const float* __restrict__ bb,
                        const float* __restrict__ S, const float* __restrict__ cc) {
    __shared__ float sW[CIN * 16];
    __shared__ float sS[16], sb[16];
    __shared__ float sc;
    int tid = threadIdx.x;
    for (int i = tid; i < CIN * 16; i += 256) sW[i] = W[i];
    if (tid < 16) { sS[tid] = S[tid]; sb[tid] = bb[tid]; }
    if (tid == 16) sc = cc[0];
    __syncthreads();

    int gid = blockIdx.x * 256 + tid;
    int b = gid >> 12, r = gid & 4095;
    int alpha = r >> 6, a = r & 63;
    const float* xb = xin + (long)b * NN_ * 20;
    long base = (long)gid * CAP;
    int cnt = g_ccnt[gid];

    float acc[CIN];
    #pragma unroll
    for (int ch = 0; ch < CIN; ch++) acc[ch] = 0.f;

    for (int k = 0; k < cnt; k++) {
        int col = g_ccol[base + k];
        float val = g_cval[base + k];
        const float* xc = xb + col * 20;
        if (CIN == 1) {
            acc[0] = fmaf(val, xc[0], acc[0]);
        } else {
            float4 c0 = *(const float4*)(xc);
            float4 c1 = *(const float4*)(xc + 4);
            float4 c2 = *(const float4*)(xc + 8);
            float4 c3 = *(const float4*)(xc + 12);
            float cs = xc[16];
            acc[0] = fmaf(val, c0.x, acc[0]);  acc[1] = fmaf(val, c0.y, acc[1]);
            acc[2] = fmaf(val, c0.z, acc[2]);  acc[3] = fmaf(val, c0.w, acc[3]);
            acc[4] = fmaf(val, c1.x, acc[4]);  acc[5] = fmaf(val, c1.y, acc[5]);
            acc[6] = fmaf(val, c1.z, acc[6]);  acc[7] = fmaf(val, c1.w, acc[7]);
            acc[8] = fmaf(val, c2.x, acc[8]);  acc[9] = fmaf(val, c2.y, acc[9]);
            acc[10] = fmaf(val, c2.z, acc[10]); acc[11] = fmaf(val, c2.w, acc[11]);
            acc[12] = fmaf(val, c3.x, acc[12]); acc[13] = fmaf(val, c3.y, acc[13]);
            acc[14] = fmaf(val, c3.z, acc[14]); acc[15] = fmaf(val, c3.w, acc[15]);
            if (CIN > 16) acc[16] = fmaf(val, cs, acc[16]);
        }
    }
    float dval = g_Kp[(long)b * NN_ + a * N_ + alpha];
    float invd = 1.0f / g_deg[gid];
    const float* xr = xb + (long)r * 20;
    float msg[CIN];
    #pragma unroll
    for (int ch = 0; ch < CIN; ch++) msg[ch] = (acc[ch] + dval * xr[ch]) * invd;

    float h[16];
    float v = sc;
    #pragma unroll
    for (int f = 0; f < 16; f++) {
        float hv = sb[f];
        #pragma unroll
        for (int ch = 0; ch < CIN; ch++) hv = fmaf(msg[ch], sW[ch * 16 + f], hv);
        hv = fmaxf(hv, 0.f);
        h[f] = hv;
        v = fmaf(hv, sS[f], v);
    }
    float* orow = xout + (long)gid * 20;
    float4 h0 = {h[0], h[1], h[2], h[3]};
    float4 h1 = {h[4], h[5], h[6], h[7]};
    float4 h2 = {h[8], h[9], h[10], h[11]};
    float4 h3 = {h[12], h[13], h[14], h[15]};
    *(float4*)(orow)      = h0;
    *(float4*)(orow + 4)  = h1;
    *(float4*)(orow + 8)  = h2;
    *(float4*)(orow + 12) = h3;
    g_vbuf[gid] = v;
}

// ---------------- 8: mid Sinkhorn (64x64, 10 iters) -> channel 16 ----------------
__global__ void __launch_bounds__(512) k_skm(float* __restrict__ xout) {
    __shared__ float M[64 * 72];
    int b = blockIdx.x, tid = threadIdx.x;
    for (int idx = tid; idx < NN_; idx += 512) {
        int q = idx >> 6, p = idx & 63;
        M[p * 72 + q] = g_vbuf[b * NN_ + idx] * 20.0f;   // 1/TAU
    }
    __syncthreads();
    int p = tid >> 3, s = tid & 7;
    for (int it = 0; it < 10; it++) {
        float m = -3.0e38f;
        for (int q = s; q < 64; q += 8) m = fmaxf(m, M[p * 72 + q]);
        m = oct_max(m);
        float sum = 0.f;
        for (int q = s; q < 64; q += 8) sum += __expf(M[p * 72 + q] - m);
        sum = oct_sum(sum);
        float lse = m + __logf(sum);
        for (int q = s; q < 64; q += 8) M[p * 72 + q] -= lse;
        __syncthreads();
        m = -3.0e38f;
        for (int rr = s; rr < 64; rr += 8) m = fmaxf(m, M[rr * 72 + p]);
        m = oct_max(m);
        sum = 0.f;
        for (int rr = s; rr < 64; rr += 8) sum += __expf(M[rr * 72 + p] - m);
        sum = oct_sum(sum);
        lse = m + __logf(sum);
        for (int rr = s; rr < 64; rr += 8) M[rr * 72 + p] -= lse;
        __syncthreads();
    }
    for (int idx = tid; idx < NN_; idx += 512) {
        int q = idx >> 6, p2 = idx & 63;
        xout[((long)b * NN_ + idx) * 20 + 16] = __expf(M[p2 * 72 + q]);
    }
}

// ---------------- 9: final 65x65 binned Sinkhorn + out + global max ----------------
__global__ void __launch_bounds__(544) k_final(const float* __restrict__ x, const float* __restrict__ Wc,
                        const float* __restrict__ bc, const float* __restrict__ binp,
                        float* __restrict__ out) {
    __shared__ float M[65 * 72];
    __shared__ float wl[17];
    __shared__ float wmax[17];
    int b = blockIdx.x, tid = threadIdx.x;
    if (tid < 17) wl[tid] = Wc[tid];
    __syncthreads();
    float bcv = bc[0];
    for (int idx = tid; idx < NN_; idx += 544) {
        const float* xr = x + ((long)b * NN_ + idx) * 20;
        float v = bcv;
        #pragma unroll
        for (int ch = 0; ch < 17; ch++) v = fmaf(xr[ch], wl[ch], v);
        int q = idx >> 6, p = idx & 63;
        M[p * 72 + q] = v;
    }
    if (tid < 65) { float bv = binp[0]; M[64 * 72 + tid] = bv; M[tid * 72 + 64] = bv; }
    __syncthreads();
    int p = tid >> 3, s = tid & 7;
    bool act = p < 65;
    for (int it = 0; it < 10; it++) {
        float m = -3.0e38f, sum = 0.f, lse;
        if (act) for (int q = s; q < 65; q += 8) m = fmaxf(m, M[p * 72 + q]);
        m = oct_max(m);
        if (act) for (int q = s; q < 65; q += 8) sum += __expf(M[p * 72 + q] - m);
        sum = oct_sum(sum);
        lse = m + __logf(sum);
        if (act) for (int q = s; q < 65; q += 8) M[p * 72 + q] -= lse;
        __syncthreads();
        m = -3.0e38f; sum = 0.f;
        if (act) for (int rr = s; rr < 65; rr += 8) m = fmaxf(m, M[rr * 72 + p]);
        m = oct_max(m);
        if (act) for (int rr = s; rr < 65; rr += 8) sum += __expf(M[rr * 72 + p] - m);
        sum = oct_sum(sum);
        lse = m + __logf(sum);
        if (act) for (int rr = s; rr < 65; rr += 8) M[rr * 72 + p] -= lse;
        __syncthreads();
    }
    float lmax = 0.f;
    for (int oidx = tid; oidx < NN_; oidx += 544) {
        int pp = oidx >> 6, qq = oidx & 63;
        float val = __expf(M[pp * 72 + qq]);
        out[(long)b * NN_ + oidx] = val;
        lmax = fmaxf(lmax, val);
    }
    lmax = warp_max(lmax);
    if ((tid & 31) == 0) wmax[tid >> 5] = lmax;
    __syncthreads();
    if (tid == 0) {
        float bm = 0.f;
        #pragma unroll
        for (int i = 0; i < 17; i++) bm = fmaxf(bm, wmax[i]);
        atomicMax(&g_maxbits, __float_as_uint(bm));
    }
}

__global__ void k_scale(float* __restrict__ out) {
    int i = blockIdx.x * blockDim.x + threadIdx.x;
    if (i < B_ * NN_) out[i] = out[i] / __uint_as_float(g_maxbits);
}

// ---------------- launch ----------------
extern "C" void kernel_launch(void* const* d_in, const int* in_sizes, int n_in,
                              void* d_out, int out_size) {
    (void)in_sizes; (void)n_in; (void)out_size;
    const float* x1    = (const float*)d_in[0];
    const float* x2    = (const float*)d_in[1];
    const float* e1    = (const float*)d_in[2];
    const float* e2    = (const float*)d_in[3];
    const float* Wp    = (const float*)d_in[4];
    const float* bp    = (const float*)d_in[5];
    const float* gamma = (const float*)d_in[6];
    const float* beta  = (const float*)d_in[7];
    const float* W0 = (const float*)d_in[8];
    const float* b0 = (const float*)d_in[9];
    const float* S0 = (const float*)d_in[10];
    const float* c0 = (const float*)d_in[11];
    const float* W1 = (const float*)d_in[12];
    const float* b1 = (const float*)d_in[13];
    const float* S1 = (const float*)d_in[14];
    const float* c1 = (const float*)d_in[15];
    const float* W2 = (const float*)d_in[16];
    const float* b2 = (const float*)d_in[17];
    const float* S2 = (const float*)d_in[18];
    const float* c2 = (const float*)d_in[19];
    const float* Wc = (const float*)d_in[20];
    const float* bc = (const float*)d_in[21];
    const float* binv = (const float*)d_in[22];
    const int* src1 = (const int*)d_in[23];
    const int* dst1 = (const int*)d_in[24];
    const int* src2 = (const int*)d_in[25];
    const int* dst2 = (const int*)d_in[26];
    float* out = (float*)d_out;

    float* g_Kp_p; cudaGetSymbolAddress((void**)&g_Kp_p, g_Kp);
    float* g_Ke_p; cudaGetSymbolAddress((void**)&g_Ke_p, g_Ke);
    float* g_xa_p; cudaGetSymbolAddress((void**)&g_xa_p, g_xa);
    float* g_xb_p; cudaGetSymbolAddress((void**)&g_xb_p, g_xb);

    k_init<<<1, 1>>>();
    k_gemm<<<dim3(32, 2, 2), 256>>>(x1, x2, e1, e2, Wp);
    k_statsc<<<32, 256>>>(bp);
    k_bn<<<512, 256>>>(gamma, beta);
    k_nt<<<dim3(2, 2, B_), 256>>>(0, 512, N_, N_, 1.0f, g_Kp_p);
    k_nt<<<dim3(6, 6, B_), 256>>>(1024, 2560, E_, E_, 0.5f, g_Ke_p);
    k_lists<<<2, 256>>>(src1, src2);
    k_build<<<4096, 256>>>(dst1, dst2);

    k_layer<1><<<128, 256>>>(g_xa_p, g_xb_p, W0, b0, S0, c0);
    k_skm<<<B_, 512>>>(g_xb_p);
    k_layer<17><<<128, 256>>>(g_xb_p, g_xa_p, W1, b1, S1, c1);
    k_skm<<<B_, 512>>>(g_xa_p);
    k_layer<17><<<128, 256>>>(g_xa_p, g_xb_p, W2, b2, S2, c2);
    k_skm<<<B_, 512>>>(g_xb_p);

    k_final<<<B_, 544>>>(g_xb_p, Wc, bc, binv, out);
    k_scale<<<128, 256>>>(out);
}